// round 1
// baseline (speedup 1.0000x reference)
#include <cuda_runtime.h>
#include <math.h>

// Problem constants (shapes are fixed for this problem instance)
#define MTAPS   41
#define OVERLAP 40
#define HOP     216
#define NFFT    256
#define PAD     20       // MTAPS/2
#define BATCH   2
#define NMODES  2
#define MAX_STEPS 4628

// Scratch: yf frames, float4 = (re_mode0, im_mode0, re_mode1, im_mode1) per (b,s,n)
__device__ float4 g_scratch[(size_t)BATCH * MAX_STEPS * NFFT];

__device__ __forceinline__ float2 cadd(float2 a, float2 b) { return make_float2(a.x + b.x, a.y + b.y); }
__device__ __forceinline__ float2 csub(float2 a, float2 b) { return make_float2(a.x - b.x, a.y - b.y); }
__device__ __forceinline__ float2 cmul(float2 a, float2 b) {
    return make_float2(a.x * b.x - a.y * b.y, a.x * b.y + a.y * b.x);
}

// Kernel 1: per (frame, batch) CTA. 256 threads.
// Forward FFT (DIF, natural->bitrev), intensity, 41-tap correlation (phi),
// pointwise multiply, inverse FFT (DIT, bitrev->natural), write frame to scratch.
__global__ __launch_bounds__(256) void eq_frame_kernel(
    const float* __restrict__ x_real,
    const float* __restrict__ x_imag,
    const float* __restrict__ task_info,
    const float* __restrict__ h_real,
    const float* __restrict__ h_imag,
    int L, int steps)
{
    const int s = blockIdx.x;   // frame index
    const int b = blockIdx.y;   // batch
    const int t = threadIdx.x;  // 0..255

    __shared__ float2 d[NMODES][NFFT];   // complex working data, both modes
    __shared__ float2 W[NFFT / 2];       // forward twiddles exp(-2*pi*i*j/256)
    __shared__ float  Ish[NFFT];         // intensity, natural frequency order
    __shared__ float2 phi_sh[NFFT];      // phi, natural frequency order
    __shared__ float  hs_r[MTAPS];
    __shared__ float  hs_i[MTAPS];
    __shared__ float  Psh;

    // ---- load frame: x stored (B, L, Nm) -> float2 per position gives both modes
    {
        const int pos = s * HOP + t;
        const float2 vr = reinterpret_cast<const float2*>(x_real)[(size_t)b * L + pos];
        const float2 vi = reinterpret_cast<const float2*>(x_imag)[(size_t)b * L + pos];
        d[0][t] = make_float2(vr.x, vi.x);
        d[1][t] = make_float2(vr.y, vi.y);
    }
    if (t < NFFT / 2) {
        float sn, cs;
        sincosf(-2.0f * 3.14159265358979323846f * (float)t / (float)NFFT, &sn, &cs);
        W[t] = make_float2(cs, sn);
    }
    if (t < MTAPS) {
        hs_r[t] = h_real[t];
        hs_i[t] = h_imag[t];
    }
    if (t == 0) {
        Psh = exp10f(task_info[b * 4] * 0.1f) * (1.0f / (float)NMODES);
    }
    __syncthreads();

    const int mode = t >> 7;        // 0..1
    const int bf   = t & 127;       // butterfly id within mode

    // ---- forward FFT: radix-2 DIF (natural input -> bit-reversed output)
    #pragma unroll
    for (int st = 0; st < 8; ++st) {
        const int span = 128 >> st;
        const int j    = bf & (span - 1);
        const int i0   = ((bf & ~(span - 1)) << 1) + j;
        const int i1   = i0 + span;
        const float2 a = d[mode][i0];
        const float2 c = d[mode][i1];
        d[mode][i0] = cadd(a, c);
        d[mode][i1] = cmul(csub(a, c), W[j << st]);
        __syncthreads();
    }

    // ---- intensity in NATURAL order via bit-reversal on write
    {
        const float2 v0 = d[0][t];
        const float2 v1 = d[1][t];
        const int k = __brev((unsigned)t) >> 24;
        Ish[k] = v0.x * v0.x + v0.y * v0.y + v1.x * v1.x + v1.y * v1.y;
    }
    __syncthreads();

    // ---- phi[k] = sum_m I[(k + m - PAD) mod 256] * h[m]   (cross-correlation, circular)
    {
        float pr = 0.0f, pi = 0.0f;
        #pragma unroll
        for (int m = 0; m < MTAPS; ++m) {
            const float Iv = Ish[(t + m - PAD) & (NFFT - 1)];
            pr = fmaf(Iv, hs_r[m], pr);
            pi = fmaf(Iv, hs_i[m], pi);
        }
        phi_sh[t] = make_float2(pr, pi);
    }
    __syncthreads();

    // ---- Y = X * (1 + i*P*phi). Data at storage pos t is freq k=brev(t).
    {
        const int k = __brev((unsigned)t) >> 24;
        const float2 ph = phi_sh[k];
        const float P  = Psh;
        const float fr = 1.0f - P * ph.y;
        const float fi = P * ph.x;
        const float2 f = make_float2(fr, fi);
        d[0][t] = cmul(d[0][t], f);
        d[1][t] = cmul(d[1][t], f);
    }
    __syncthreads();

    // ---- inverse FFT: radix-2 DIT (bit-reversed input -> natural output), conj twiddles
    #pragma unroll
    for (int st = 0; st < 8; ++st) {
        const int span = 1 << st;
        const int j    = bf & (span - 1);
        const int i0   = ((bf & ~(span - 1)) << 1) + j;
        const int i1   = i0 + span;
        const float2 wf = W[j << (7 - st)];
        const float2 wc = make_float2(wf.x, -wf.y);       // conjugate for inverse
        const float2 a  = d[mode][i0];
        const float2 tm = cmul(d[mode][i1], wc);
        d[mode][i0] = cadd(a, tm);
        d[mode][i1] = csub(a, tm);
        __syncthreads();
    }

    // ---- scale by 1/N and write frame to scratch (coalesced float4)
    {
        const float sc = 1.0f / (float)NFFT;
        float4 o;
        o.x = d[0][t].x * sc;
        o.y = d[0][t].y * sc;
        o.z = d[1][t].x * sc;
        o.w = d[1][t].y * sc;
        g_scratch[((size_t)b * steps + s) * NFFT + t] = o;
    }
}

// Kernel 2: overlap-add gather + normalize + slice.
// Each thread handles one (b, l) output position: both modes, real+imag = one float4.
__global__ __launch_bounds__(256) void ola_gather_kernel(
    float* __restrict__ out, int L, int steps)
{
    const int idx = blockIdx.x * blockDim.x + threadIdx.x;
    const int Lout = L - OVERLAP;
    const int total = BATCH * Lout;
    if (idx >= total) return;

    const int b = idx / Lout;
    const int l = idx - b * Lout;
    const int lp = l + PAD;        // position in the full (unsliced) signal

    const int s0 = lp / HOP;
    float4 acc = make_float4(0.f, 0.f, 0.f, 0.f);
    int cnt = 0;

    #pragma unroll
    for (int ds = 0; ds < 2; ++ds) {
        const int s = s0 - ds;
        if (s < 0 || s >= steps) continue;
        const int n = lp - s * HOP;
        if (n < 0 || n >= NFFT) continue;
        const float4 v = g_scratch[((size_t)b * steps + s) * NFFT + n];
        acc.x += v.x; acc.y += v.y; acc.z += v.z; acc.w += v.w;
        ++cnt;
    }

    const float inv = 1.0f / (float)cnt;
    float4 o;
    o.x = acc.x * inv;  // mode0 real
    o.y = acc.y * inv;  // mode0 imag
    o.z = acc.z * inv;  // mode1 real
    o.w = acc.w * inv;  // mode1 imag
    reinterpret_cast<float4*>(out)[(size_t)b * Lout + l] = o;
}

extern "C" void kernel_launch(void* const* d_in, const int* in_sizes, int n_in,
                              void* d_out, int out_size)
{
    const float* x_real    = (const float*)d_in[0];
    const float* x_imag    = (const float*)d_in[1];
    const float* task_info = (const float*)d_in[2];
    const float* h_real    = (const float*)d_in[3];
    const float* h_imag    = (const float*)d_in[4];

    const int L = in_sizes[0] / (BATCH * NMODES);
    int steps = (L - NFFT) / HOP + 1;
    if (steps > MAX_STEPS) steps = MAX_STEPS;

    dim3 grid1(steps, BATCH);
    eq_frame_kernel<<<grid1, 256>>>(x_real, x_imag, task_info, h_real, h_imag, L, steps);

    const int total = BATCH * (L - OVERLAP);
    ola_gather_kernel<<<(total + 255) / 256, 256>>>((float*)d_out, L, steps);
}

// round 2
// speedup vs baseline: 2.4360x; 2.4360x over previous
#include <cuda_runtime.h>
#include <math.h>

// Fixed problem constants
#define MTAPS   41
#define OVERLAP 40
#define HOP     216
#define NFFT    256
#define PAD     20
#define BATCH   2
#define MAX_STEPS 4628
#define TWO_PI_F 6.283185307179586f

// C~[n] = (1/256) * sum_m h[m] * e^{-2*pi*i*n*(m-20)/256}  (natural order n)
__device__ float2 g_C[NFFT];
// Edge scratch: head = frame samples n in [0,40), tail = n in [216,256)
__device__ float4 g_head[(size_t)BATCH * MAX_STEPS * OVERLAP];
__device__ float4 g_tail[(size_t)BATCH * MAX_STEPS * OVERLAP];

__device__ __forceinline__ float2 cmulf(float2 a, float2 b) {
    return make_float2(fmaf(-a.y, b.y, a.x * b.x), fmaf(a.y, b.x, a.x * b.y));
}
__device__ __forceinline__ float2 cmulj(float2 a, float2 b) { // a * conj(b)
    return make_float2(fmaf(a.y, b.y, a.x * b.x), fmaf(a.y, b.x, -a.x * b.y));
}
__device__ __forceinline__ float2 cadd2(float2 a, float2 b) { return make_float2(a.x + b.x, a.y + b.y); }
__device__ __forceinline__ float2 csub2(float2 a, float2 b) { return make_float2(a.x - b.x, a.y - b.y); }

#define RC2 0.70710678118654752440f
// multiply by e^{-i*pi/4} = (c, -c)
__device__ __forceinline__ float2 mW8_1(float2 v)  { return make_float2(RC2 * (v.x + v.y), RC2 * (v.y - v.x)); }
// multiply by e^{-3i*pi/4} = (-c, -c)
__device__ __forceinline__ float2 mW8_3(float2 v)  { return make_float2(RC2 * (v.y - v.x), -RC2 * (v.x + v.y)); }
// multiply by -i
__device__ __forceinline__ float2 mNI(float2 v)    { return make_float2(v.y, -v.x); }
// multiply by +i
__device__ __forceinline__ float2 mPI(float2 v)    { return make_float2(-v.y, v.x); }
// multiply by e^{+i*pi/4} = (c, c)
__device__ __forceinline__ float2 mW8_1c(float2 v) { return make_float2(RC2 * (v.x - v.y), RC2 * (v.x + v.y)); }
// multiply by e^{+3i*pi/4} = (-c, c)
__device__ __forceinline__ float2 mW8_3c(float2 v) { return make_float2(-RC2 * (v.x + v.y), RC2 * (v.x - v.y)); }

// ---- in-register 8-pt DIF DFT over slots (natural r in -> bitrev k1 slots out)
__device__ __forceinline__ void reg_dif8(float2 a[8]) {
    float2 t0 = cadd2(a[0], a[4]), t4 = csub2(a[0], a[4]);
    float2 t1 = cadd2(a[1], a[5]), t5 = mW8_1(csub2(a[1], a[5]));
    float2 t2 = cadd2(a[2], a[6]), t6 = mNI(csub2(a[2], a[6]));
    float2 t3 = cadd2(a[3], a[7]), t7 = mW8_3(csub2(a[3], a[7]));
    float2 u0 = cadd2(t0, t2), u2 = csub2(t0, t2);
    float2 u1 = cadd2(t1, t3), u3 = mNI(csub2(t1, t3));
    float2 u4 = cadd2(t4, t6), u6 = csub2(t4, t6);
    float2 u5 = cadd2(t5, t7), u7 = mNI(csub2(t5, t7));
    a[0] = cadd2(u0, u1); a[1] = csub2(u0, u1);
    a[2] = cadd2(u2, u3); a[3] = csub2(u2, u3);
    a[4] = cadd2(u4, u5); a[5] = csub2(u4, u5);
    a[6] = cadd2(u6, u7); a[7] = csub2(u6, u7);
}

// ---- in-register 8-pt DIT inverse (bitrev k1 slots in -> natural r out), conj twiddles
__device__ __forceinline__ void reg_dit8_inv(float2 a[8]) {
    float2 t0 = cadd2(a[0], a[1]), t1 = csub2(a[0], a[1]);
    float2 t2 = cadd2(a[2], a[3]), t3 = csub2(a[2], a[3]);
    float2 t4 = cadd2(a[4], a[5]), t5 = csub2(a[4], a[5]);
    float2 t6 = cadd2(a[6], a[7]), t7 = csub2(a[6], a[7]);
    float2 b;
    float2 u0 = cadd2(t0, t2), u2 = csub2(t0, t2);
    b = mPI(t3);
    float2 u1 = cadd2(t1, b), u3 = csub2(t1, b);
    float2 u4 = cadd2(t4, t6), u6 = csub2(t4, t6);
    b = mPI(t7);
    float2 u5 = cadd2(t5, b), u7 = csub2(t5, b);
    a[0] = cadd2(u0, u4); a[4] = csub2(u0, u4);
    b = mW8_1c(u5);
    a[1] = cadd2(u1, b); a[5] = csub2(u1, b);
    b = mPI(u6);
    a[2] = cadd2(u2, b); a[6] = csub2(u2, b);
    b = mW8_3c(u7);
    a[3] = cadd2(u3, b); a[7] = csub2(u3, b);
}

// ---- cross-lane 32-pt DIF (natural lanes in -> bitrev lanes out)
__device__ __forceinline__ void xlane_fwd(float2 a[8], int lane, const float2 wcl[5]) {
    #pragma unroll
    for (int st = 0; st < 5; ++st) {
        const int m = 16 >> st;
        const float2 w = wcl[st];
        const bool up = (lane & m) != 0;
        #pragma unroll
        for (int i = 0; i < 8; ++i) {
            float2 o;
            o.x = __shfl_xor_sync(0xffffffffu, a[i].x, m);
            o.y = __shfl_xor_sync(0xffffffffu, a[i].y, m);
            float2 sum = cadd2(a[i], o);
            float2 dif = csub2(o, a[i]);       // partner - self (= a - b on upper lane)
            a[i] = up ? cmulf(dif, w) : sum;
        }
    }
}

// ---- cross-lane 32-pt inverse DIT (bitrev lanes in -> natural lanes out), conj twiddles
__device__ __forceinline__ void xlane_inv(float2 a[8], int lane, const float2 wcl[5]) {
    #pragma unroll
    for (int st = 0; st < 5; ++st) {
        const int m = 1 << st;
        const float2 w = wcl[4 - st];          // conj applied via cmulj
        const bool up = (lane & m) != 0;
        #pragma unroll
        for (int i = 0; i < 8; ++i) {
            float2 v = a[i];
            float2 vm = cmulj(v, w);
            v = up ? vm : v;
            float2 o;
            o.x = __shfl_xor_sync(0xffffffffu, v.x, m);
            o.y = __shfl_xor_sync(0xffffffffu, v.y, m);
            a[i] = up ? csub2(o, v) : cadd2(v, o);
        }
    }
}

// forward per-lane twiddle: slot s holds k1=brev3(s), multiply by wp[k1]
__device__ __forceinline__ void twiddle_fwd(float2 a[8], const float2 wp[8]) {
    a[1] = cmulf(a[1], wp[4]); a[2] = cmulf(a[2], wp[2]); a[3] = cmulf(a[3], wp[6]);
    a[4] = cmulf(a[4], wp[1]); a[5] = cmulf(a[5], wp[5]); a[6] = cmulf(a[6], wp[3]);
    a[7] = cmulf(a[7], wp[7]);
}
__device__ __forceinline__ void twiddle_inv(float2 a[8], const float2 wp[8]) {
    a[1] = cmulj(a[1], wp[4]); a[2] = cmulj(a[2], wp[2]); a[3] = cmulj(a[3], wp[6]);
    a[4] = cmulj(a[4], wp[1]); a[5] = cmulj(a[5], wp[5]); a[6] = cmulj(a[6], wp[3]);
    a[7] = cmulj(a[7], wp[7]);
}

// full 256-pt forward: input natural n = lane + 32*r (slot r), output bin k = brev3(slot) + 8*brev5(lane)
__device__ __forceinline__ void fft256_fwd(float2 a[8], int lane, const float2 wp[8], const float2 wcl[5]) {
    reg_dif8(a);
    twiddle_fwd(a, wp);
    xlane_fwd(a, lane, wcl);
}
// full 256-pt inverse (RAW: no 1/N): input bin layout as above, output natural n = lane + 32*r
__device__ __forceinline__ void fft256_inv(float2 a[8], int lane, const float2 wp[8], const float2 wcl[5]) {
    xlane_inv(a, lane, wcl);
    twiddle_inv(a, wp);
    reg_dit8_inv(a);
}

// ---------------- setup: C~ table (once per launch, trivial cost) ----------------
__global__ void setup_C_kernel(const float* __restrict__ h_real, const float* __restrict__ h_imag) {
    const int n = threadIdx.x;
    float sr = 0.0f, si = 0.0f;
    for (int m = 0; m < MTAPS; ++m) {
        int e = (n * (m - PAD)) % NFFT;      // exact integer reduction
        if (e < 0) e += NFFT;
        float sn, cs;
        sincosf(-(TWO_PI_F / NFFT) * (float)e, &sn, &cs);
        const float hr = h_real[m], hi = h_imag[m];
        sr += hr * cs - hi * sn;
        si += hr * sn + hi * cs;
    }
    g_C[n] = make_float2(sr * (1.0f / NFFT), si * (1.0f / NFFT));
}

// ---------------- kernel 1: warp per (batch, frame) ----------------
__global__ __launch_bounds__(128) void eq_frame_kernel(
    const float* __restrict__ x_real,
    const float* __restrict__ x_imag,
    const float* __restrict__ task_info,
    float* __restrict__ out,
    int L, int steps)
{
    const int w = blockIdx.x * 4 + (threadIdx.x >> 5);
    const int lane = threadIdx.x & 31;
    if (w >= BATCH * steps) return;
    const int b = w / steps;
    const int s = w - b * steps;

    // cross-lane stage twiddles: stage m: e^{-2*pi*i*(lane&(m-1))/(2m)}
    float2 wcl[5];
    #pragma unroll
    for (int st = 0; st < 5; ++st) {
        const int m = 16 >> st;
        const float ang = -(TWO_PI_F / (2.0f * (float)m)) * (float)(lane & (m - 1));
        __sincosf(ang, &wcl[st].y, &wcl[st].x);
    }
    // per-lane twiddle powers w1^k, w1 = e^{-2*pi*i*lane/256}
    float2 wp[8];
    wp[0] = make_float2(1.0f, 0.0f);
    __sincosf(-(TWO_PI_F / 256.0f) * (float)lane, &wp[1].y, &wp[1].x);
    wp[2] = cmulf(wp[1], wp[1]);
    wp[3] = cmulf(wp[2], wp[1]);
    wp[4] = cmulf(wp[2], wp[2]);
    wp[5] = cmulf(wp[4], wp[1]);
    wp[6] = cmulf(wp[3], wp[3]);
    wp[7] = cmulf(wp[4], wp[3]);

    // ---- load frame, both modes: n = lane + 32*r
    float2 X0[8], X1[8];
    const float2* xr2 = reinterpret_cast<const float2*>(x_real) + (size_t)b * L;
    const float2* xi2 = reinterpret_cast<const float2*>(x_imag) + (size_t)b * L;
    const int base = s * HOP + lane;
    #pragma unroll
    for (int r = 0; r < 8; ++r) {
        const float2 vr = __ldg(&xr2[base + 32 * r]);
        const float2 vi = __ldg(&xi2[base + 32 * r]);
        X0[r] = make_float2(vr.x, vi.x);
        X1[r] = make_float2(vr.y, vi.y);
    }

    // ---- forward FFTs
    fft256_fwd(X0, lane, wp, wcl);
    fft256_fwd(X1, lane, wp, wcl);

    // ---- intensity per bin (bin layout), imag = 0
    float2 Iv[8];
    #pragma unroll
    for (int i = 0; i < 8; ++i) {
        float t = X0[i].x * X0[i].x;
        t = fmaf(X0[i].y, X0[i].y, t);
        t = fmaf(X1[i].x, X1[i].x, t);
        t = fmaf(X1[i].y, X1[i].y, t);
        Iv[i] = make_float2(t, 0.0f);
    }

    // ---- phi = FWD( INVraw(I) .* C~ )  (convolution theorem over frequency bins)
    fft256_inv(Iv, lane, wp, wcl);       // J[n], natural order
    #pragma unroll
    for (int r = 0; r < 8; ++r) {
        Iv[r] = cmulf(Iv[r], g_C[lane + 32 * r]);
    }
    fft256_fwd(Iv, lane, wp, wcl);       // phi, bin layout (aligned with X bins)

    // ---- Y = X * (1 + i*P*phi)
    const float P = exp10f(task_info[b * 4] * 0.1f) * 0.5f;
    #pragma unroll
    for (int i = 0; i < 8; ++i) {
        const float2 f = make_float2(fmaf(-P, Iv[i].y, 1.0f), P * Iv[i].x);
        X0[i] = cmulf(X0[i], f);
        X1[i] = cmulf(X1[i], f);
    }

    // ---- inverse FFTs -> time domain, natural n = lane + 32*r
    fft256_inv(X0, lane, wp, wcl);
    fft256_inv(X1, lane, wp, wcl);

    // ---- write: direct output for singly-covered samples, edges to scratch
    const float sc = 1.0f / (float)NFFT;
    const int Lout = L - OVERLAP;
    float4* out4 = reinterpret_cast<float4*>(out) + (size_t)b * Lout;
    float4* headp = g_head + (size_t)(b * steps + s) * OVERLAP;
    float4* tailp = g_tail + (size_t)(b * steps + s) * OVERLAP;
    #pragma unroll
    for (int r = 0; r < 8; ++r) {
        const int n = lane + 32 * r;
        float4 v;
        v.x = X0[r].x * sc; v.y = X0[r].y * sc;
        v.z = X1[r].x * sc; v.w = X1[r].y * sc;
        if (n < OVERLAP && s > 0) {
            headp[n] = v;
        } else if (n >= HOP && s < steps - 1) {
            tailp[n - HOP] = v;
        } else {
            const int lp = s * HOP + n;
            if (lp >= PAD && lp < L - PAD) out4[lp - PAD] = v;
        }
    }
}

// ---------------- kernel 2: combine the 40-sample overlap edges ----------------
__global__ __launch_bounds__(256) void combine_edges_kernel(float* __restrict__ out, int L, int steps) {
    const int idx = blockIdx.x * blockDim.x + threadIdx.x;
    const int per_b = (steps - 1) * OVERLAP;
    if (idx >= BATCH * per_b) return;
    const int b = idx / per_b;
    const int t = idx - b * per_b;
    const int s = t / OVERLAP;          // 0 .. steps-2
    const int e = t - s * OVERLAP;

    const float4 a = g_tail[(size_t)(b * steps + s) * OVERLAP + e];
    const float4 h = g_head[(size_t)(b * steps + s + 1) * OVERLAP + e];
    float4 v;
    v.x = (a.x + h.x) * 0.5f;
    v.y = (a.y + h.y) * 0.5f;
    v.z = (a.z + h.z) * 0.5f;
    v.w = (a.w + h.w) * 0.5f;

    const int lp = (s + 1) * HOP + e;
    const int Lout = L - OVERLAP;
    reinterpret_cast<float4*>(out)[(size_t)b * Lout + lp - PAD] = v;
}

extern "C" void kernel_launch(void* const* d_in, const int* in_sizes, int n_in,
                              void* d_out, int out_size)
{
    const float* x_real    = (const float*)d_in[0];
    const float* x_imag    = (const float*)d_in[1];
    const float* task_info = (const float*)d_in[2];
    const float* h_real    = (const float*)d_in[3];
    const float* h_imag    = (const float*)d_in[4];

    const int L = in_sizes[0] / (BATCH * 2);
    int steps = (L - NFFT) / HOP + 1;
    if (steps > MAX_STEPS) steps = MAX_STEPS;

    setup_C_kernel<<<1, NFFT>>>(h_real, h_imag);

    const int warps = BATCH * steps;
    eq_frame_kernel<<<(warps + 3) / 4, 128>>>(x_real, x_imag, task_info, (float*)d_out, L, steps);

    const int total2 = BATCH * (steps - 1) * OVERLAP;
    combine_edges_kernel<<<(total2 + 255) / 256, 256>>>((float*)d_out, L, steps);
}

// round 3
// speedup vs baseline: 2.8170x; 1.1564x over previous
#include <cuda_runtime.h>
#include <math.h>

// Fixed problem constants
#define MTAPS   41
#define OVERLAP 40
#define HOP     216
#define NFFT    256
#define PAD     20
#define BATCH   2
#define MAX_STEPS 4628
#define TWO_PI_F 6.283185307179586f

typedef unsigned long long ull;

// C~[n] = (1/256) * sum_m h[m] * e^{-2*pi*i*n*(m-20)/256}  (natural order n)
__device__ float2 g_C[NFFT];
// Edge scratch: head = frame samples n in [0,40), tail = n in [216,256)
__device__ float4 g_head[(size_t)BATCH * MAX_STEPS * OVERLAP];
__device__ float4 g_tail[(size_t)BATCH * MAX_STEPS * OVERLAP];

// ======================= scalar complex helpers (Iv chain) =======================
__device__ __forceinline__ float2 cmulf(float2 a, float2 b) {
    return make_float2(fmaf(-a.y, b.y, a.x * b.x), fmaf(a.y, b.x, a.x * b.y));
}
__device__ __forceinline__ float2 cmulj(float2 a, float2 b) { // a * conj(b)
    return make_float2(fmaf(a.y, b.y, a.x * b.x), fmaf(a.y, b.x, -a.x * b.y));
}
__device__ __forceinline__ float2 cadd2(float2 a, float2 b) { return make_float2(a.x + b.x, a.y + b.y); }
__device__ __forceinline__ float2 csub2(float2 a, float2 b) { return make_float2(a.x - b.x, a.y - b.y); }

#define RC2 0.70710678118654752440f
__device__ __forceinline__ float2 mW8_1(float2 v)  { return make_float2(RC2 * (v.x + v.y), RC2 * (v.y - v.x)); }
__device__ __forceinline__ float2 mW8_3(float2 v)  { return make_float2(RC2 * (v.y - v.x), -RC2 * (v.x + v.y)); }
__device__ __forceinline__ float2 mNI(float2 v)    { return make_float2(v.y, -v.x); }
__device__ __forceinline__ float2 mPI(float2 v)    { return make_float2(-v.y, v.x); }
__device__ __forceinline__ float2 mW8_1c(float2 v) { return make_float2(RC2 * (v.x - v.y), RC2 * (v.x + v.y)); }
__device__ __forceinline__ float2 mW8_3c(float2 v) { return make_float2(-RC2 * (v.x + v.y), RC2 * (v.x - v.y)); }

// ======================= f32x2 packed helpers (mode-packed FFTs) =======================
__device__ __forceinline__ ull pk2(float x, float y) {
    ull u; asm("mov.b64 %0, {%1,%2};" : "=l"(u) : "f"(x), "f"(y)); return u;
}
__device__ __forceinline__ float2 unpk(ull u) {
    float2 a; asm("mov.b64 {%0,%1}, %2;" : "=f"(a.x), "=f"(a.y) : "l"(u)); return a;
}
__device__ __forceinline__ ull splat(float x) { return pk2(x, x); }
__device__ __forceinline__ ull padd(ull a, ull b) {
    ull r; asm("add.rn.f32x2 %0, %1, %2;" : "=l"(r) : "l"(a), "l"(b)); return r;
}
__device__ __forceinline__ ull psub(ull a, ull b) {
    ull r; asm("sub.rn.f32x2 %0, %1, %2;" : "=l"(r) : "l"(a), "l"(b)); return r;
}
__device__ __forceinline__ ull pmul(ull a, ull b) {
    ull r; asm("mul.rn.f32x2 %0, %1, %2;" : "=l"(r) : "l"(a), "l"(b)); return r;
}
__device__ __forceinline__ ull pfma(ull a, ull b, ull c) {
    ull r; asm("fma.rn.f32x2 %0, %1, %2, %3;" : "=l"(r) : "l"(a), "l"(b), "l"(c)); return r;
}
// bit constants: RC2f = 0x3F3504F3
#define C2P  0x3F3504F33F3504F3ULL
#define CN2P 0xBF3504F3BF3504F3ULL
#define ZP   0x0000000000000000ULL

__device__ __forceinline__ ull pneg(ull a) { return psub(ZP, a); }

// packed complex (Re-pair, Im-pair) * scalar complex w  -> in place
__device__ __forceinline__ void pcmul(ull& Re, ull& Im, float wx, float wy) {
    const ull sx  = splat(wx);
    const ull sy  = splat(wy);
    const ull syn = splat(-wy);
    const ull r = pfma(Re, sx, pmul(Im, syn));
    const ull i = pfma(Re, sy, pmul(Im, sx));
    Re = r; Im = i;
}
// packed complex * conj(w)
__device__ __forceinline__ void pcmulj(ull& Re, ull& Im, float wx, float wy) {
    const ull sx  = splat(wx);
    const ull sy  = splat(wy);
    const ull syn = splat(-wy);
    const ull r = pfma(Re, sx, pmul(Im, sy));
    const ull i = pfma(Im, sx, pmul(Re, syn));
    Re = r; Im = i;
}
__device__ __forceinline__ ull pshfl_xor(ull v, int m) {
    unsigned lo = (unsigned)v, hi = (unsigned)(v >> 32);
    lo = __shfl_xor_sync(0xffffffffu, lo, m);
    hi = __shfl_xor_sync(0xffffffffu, hi, m);
    return ((ull)hi << 32) | (ull)lo;
}

// packed rotations (Re', Im') for multiply by fixed 8th roots
__device__ __forceinline__ void pW8_1(ull& Re, ull& Im) {   // * e^{-i pi/4}
    const ull r = pmul(padd(Re, Im), (ull)C2P);
    const ull i = pmul(psub(Im, Re), (ull)C2P);
    Re = r; Im = i;
}
__device__ __forceinline__ void pW8_3(ull& Re, ull& Im) {   // * e^{-3i pi/4}
    const ull r = pmul(psub(Im, Re), (ull)C2P);
    const ull i = pmul(padd(Re, Im), (ull)CN2P);
    Re = r; Im = i;
}
__device__ __forceinline__ void pNI(ull& Re, ull& Im) {     // * -i
    const ull r = Im; const ull i = pneg(Re); Re = r; Im = i;
}
__device__ __forceinline__ void pPI(ull& Re, ull& Im) {     // * +i
    const ull r = pneg(Im); const ull i = Re; Re = r; Im = i;
}
__device__ __forceinline__ void pW8_1c(ull& Re, ull& Im) {  // * e^{+i pi/4}
    const ull r = pmul(psub(Re, Im), (ull)C2P);
    const ull i = pmul(padd(Re, Im), (ull)C2P);
    Re = r; Im = i;
}
__device__ __forceinline__ void pW8_3c(ull& Re, ull& Im) {  // * e^{+3i pi/4}
    const ull r = pmul(padd(Re, Im), (ull)CN2P);
    const ull i = pmul(psub(Re, Im), (ull)C2P);
    Re = r; Im = i;
}

// ======================= scalar 256-pt FFT (Iv chain) =======================
__device__ __forceinline__ void reg_dif8(float2 a[8]) {
    float2 t0 = cadd2(a[0], a[4]), t4 = csub2(a[0], a[4]);
    float2 t1 = cadd2(a[1], a[5]), t5 = mW8_1(csub2(a[1], a[5]));
    float2 t2 = cadd2(a[2], a[6]), t6 = mNI(csub2(a[2], a[6]));
    float2 t3 = cadd2(a[3], a[7]), t7 = mW8_3(csub2(a[3], a[7]));
    float2 u0 = cadd2(t0, t2), u2 = csub2(t0, t2);
    float2 u1 = cadd2(t1, t3), u3 = mNI(csub2(t1, t3));
    float2 u4 = cadd2(t4, t6), u6 = csub2(t4, t6);
    float2 u5 = cadd2(t5, t7), u7 = mNI(csub2(t5, t7));
    a[0] = cadd2(u0, u1); a[1] = csub2(u0, u1);
    a[2] = cadd2(u2, u3); a[3] = csub2(u2, u3);
    a[4] = cadd2(u4, u5); a[5] = csub2(u4, u5);
    a[6] = cadd2(u6, u7); a[7] = csub2(u6, u7);
}
__device__ __forceinline__ void reg_dit8_inv(float2 a[8]) {
    float2 t0 = cadd2(a[0], a[1]), t1 = csub2(a[0], a[1]);
    float2 t2 = cadd2(a[2], a[3]), t3 = csub2(a[2], a[3]);
    float2 t4 = cadd2(a[4], a[5]), t5 = csub2(a[4], a[5]);
    float2 t6 = cadd2(a[6], a[7]), t7 = csub2(a[6], a[7]);
    float2 b;
    float2 u0 = cadd2(t0, t2), u2 = csub2(t0, t2);
    b = mPI(t3);
    float2 u1 = cadd2(t1, b), u3 = csub2(t1, b);
    float2 u4 = cadd2(t4, t6), u6 = csub2(t4, t6);
    b = mPI(t7);
    float2 u5 = cadd2(t5, b), u7 = csub2(t5, b);
    a[0] = cadd2(u0, u4); a[4] = csub2(u0, u4);
    b = mW8_1c(u5);
    a[1] = cadd2(u1, b); a[5] = csub2(u1, b);
    b = mPI(u6);
    a[2] = cadd2(u2, b); a[6] = csub2(u2, b);
    b = mW8_3c(u7);
    a[3] = cadd2(u3, b); a[7] = csub2(u3, b);
}
__device__ __forceinline__ void xlane_fwd(float2 a[8], int lane, const float2 wcl[5]) {
    #pragma unroll
    for (int st = 0; st < 5; ++st) {
        const int m = 16 >> st;
        const float2 w = wcl[st];
        const bool up = (lane & m) != 0;
        #pragma unroll
        for (int i = 0; i < 8; ++i) {
            float2 o;
            o.x = __shfl_xor_sync(0xffffffffu, a[i].x, m);
            o.y = __shfl_xor_sync(0xffffffffu, a[i].y, m);
            float2 sum = cadd2(a[i], o);
            float2 dif = csub2(o, a[i]);
            a[i] = up ? cmulf(dif, w) : sum;
        }
    }
}
__device__ __forceinline__ void xlane_inv(float2 a[8], int lane, const float2 wcl[5]) {
    #pragma unroll
    for (int st = 0; st < 5; ++st) {
        const int m = 1 << st;
        const float2 w = wcl[4 - st];
        const bool up = (lane & m) != 0;
        #pragma unroll
        for (int i = 0; i < 8; ++i) {
            float2 v = a[i];
            float2 vm = cmulj(v, w);
            v = up ? vm : v;
            float2 o;
            o.x = __shfl_xor_sync(0xffffffffu, v.x, m);
            o.y = __shfl_xor_sync(0xffffffffu, v.y, m);
            a[i] = up ? csub2(o, v) : cadd2(v, o);
        }
    }
}
__device__ __forceinline__ void twiddle_fwd(float2 a[8], const float2 wp[8]) {
    a[1] = cmulf(a[1], wp[4]); a[2] = cmulf(a[2], wp[2]); a[3] = cmulf(a[3], wp[6]);
    a[4] = cmulf(a[4], wp[1]); a[5] = cmulf(a[5], wp[5]); a[6] = cmulf(a[6], wp[3]);
    a[7] = cmulf(a[7], wp[7]);
}
__device__ __forceinline__ void twiddle_inv(float2 a[8], const float2 wp[8]) {
    a[1] = cmulj(a[1], wp[4]); a[2] = cmulj(a[2], wp[2]); a[3] = cmulj(a[3], wp[6]);
    a[4] = cmulj(a[4], wp[1]); a[5] = cmulj(a[5], wp[5]); a[6] = cmulj(a[6], wp[3]);
    a[7] = cmulj(a[7], wp[7]);
}
__device__ __forceinline__ void fft256_fwd(float2 a[8], int lane, const float2 wp[8], const float2 wcl[5]) {
    reg_dif8(a); twiddle_fwd(a, wp); xlane_fwd(a, lane, wcl);
}
__device__ __forceinline__ void fft256_inv(float2 a[8], int lane, const float2 wp[8], const float2 wcl[5]) {
    xlane_inv(a, lane, wcl); twiddle_inv(a, wp); reg_dit8_inv(a);
}

// ======================= packed (both modes) 256-pt FFT =======================
__device__ __forceinline__ void reg_dif8_p(ull R[8], ull I[8]) {
    ull r0 = padd(R[0], R[4]), i0 = padd(I[0], I[4]);
    ull r4 = psub(R[0], R[4]), i4 = psub(I[0], I[4]);
    ull r1 = padd(R[1], R[5]), i1 = padd(I[1], I[5]);
    ull r5 = psub(R[1], R[5]), i5 = psub(I[1], I[5]); pW8_1(r5, i5);
    ull r2 = padd(R[2], R[6]), i2 = padd(I[2], I[6]);
    ull r6 = psub(R[2], R[6]), i6 = psub(I[2], I[6]); pNI(r6, i6);
    ull r3 = padd(R[3], R[7]), i3 = padd(I[3], I[7]);
    ull r7 = psub(R[3], R[7]), i7 = psub(I[3], I[7]); pW8_3(r7, i7);

    ull ur0 = padd(r0, r2), ui0 = padd(i0, i2);
    ull ur2 = psub(r0, r2), ui2 = psub(i0, i2);
    ull ur1 = padd(r1, r3), ui1 = padd(i1, i3);
    ull ur3 = psub(r1, r3), ui3 = psub(i1, i3); pNI(ur3, ui3);
    ull ur4 = padd(r4, r6), ui4 = padd(i4, i6);
    ull ur6 = psub(r4, r6), ui6 = psub(i4, i6);
    ull ur5 = padd(r5, r7), ui5 = padd(i5, i7);
    ull ur7 = psub(r5, r7), ui7 = psub(i5, i7); pNI(ur7, ui7);

    R[0] = padd(ur0, ur1); I[0] = padd(ui0, ui1);
    R[1] = psub(ur0, ur1); I[1] = psub(ui0, ui1);
    R[2] = padd(ur2, ur3); I[2] = padd(ui2, ui3);
    R[3] = psub(ur2, ur3); I[3] = psub(ui2, ui3);
    R[4] = padd(ur4, ur5); I[4] = padd(ui4, ui5);
    R[5] = psub(ur4, ur5); I[5] = psub(ui4, ui5);
    R[6] = padd(ur6, ur7); I[6] = padd(ui6, ui7);
    R[7] = psub(ur6, ur7); I[7] = psub(ui6, ui7);
}
__device__ __forceinline__ void reg_dit8_inv_p(ull R[8], ull I[8]) {
    ull tr0 = padd(R[0], R[1]), ti0 = padd(I[0], I[1]);
    ull tr1 = psub(R[0], R[1]), ti1 = psub(I[0], I[1]);
    ull tr2 = padd(R[2], R[3]), ti2 = padd(I[2], I[3]);
    ull tr3 = psub(R[2], R[3]), ti3 = psub(I[2], I[3]);
    ull tr4 = padd(R[4], R[5]), ti4 = padd(I[4], I[5]);
    ull tr5 = psub(R[4], R[5]), ti5 = psub(I[4], I[5]);
    ull tr6 = padd(R[6], R[7]), ti6 = padd(I[6], I[7]);
    ull tr7 = psub(R[6], R[7]), ti7 = psub(I[6], I[7]);

    ull ur0 = padd(tr0, tr2), ui0 = padd(ti0, ti2);
    ull ur2 = psub(tr0, tr2), ui2 = psub(ti0, ti2);
    pPI(tr3, ti3);
    ull ur1 = padd(tr1, tr3), ui1 = padd(ti1, ti3);
    ull ur3 = psub(tr1, tr3), ui3 = psub(ti1, ti3);
    ull ur4 = padd(tr4, tr6), ui4 = padd(ti4, ti6);
    ull ur6 = psub(tr4, tr6), ui6 = psub(ti4, ti6);
    pPI(tr7, ti7);
    ull ur5 = padd(tr5, tr7), ui5 = padd(ti5, ti7);
    ull ur7 = psub(tr5, tr7), ui7 = psub(ti5, ti7);

    R[0] = padd(ur0, ur4); I[0] = padd(ui0, ui4);
    R[4] = psub(ur0, ur4); I[4] = psub(ui0, ui4);
    pW8_1c(ur5, ui5);
    R[1] = padd(ur1, ur5); I[1] = padd(ui1, ui5);
    R[5] = psub(ur1, ur5); I[5] = psub(ui1, ui5);
    pPI(ur6, ui6);
    R[2] = padd(ur2, ur6); I[2] = padd(ui2, ui6);
    R[6] = psub(ur2, ur6); I[6] = psub(ui2, ui6);
    pW8_3c(ur7, ui7);
    R[3] = padd(ur3, ur7); I[3] = padd(ui3, ui7);
    R[7] = psub(ur3, ur7); I[7] = psub(ui3, ui7);
}
__device__ __forceinline__ void xlane_fwd_p(ull R[8], ull I[8], int lane, const float2 wcl[5]) {
    #pragma unroll
    for (int st = 0; st < 5; ++st) {
        const int m = 16 >> st;
        const ull sx  = splat(wcl[st].x);
        const ull sy  = splat(wcl[st].y);
        const ull syn = splat(-wcl[st].y);
        const bool up = (lane & m) != 0;
        #pragma unroll
        for (int i = 0; i < 8; ++i) {
            const ull oR = pshfl_xor(R[i], m);
            const ull oI = pshfl_xor(I[i], m);
            const ull sR = padd(R[i], oR), sI = padd(I[i], oI);
            const ull dR = psub(oR, R[i]), dI = psub(oI, I[i]);
            const ull mR = pfma(dR, sx, pmul(dI, syn));
            const ull mI = pfma(dR, sy, pmul(dI, sx));
            R[i] = up ? mR : sR;
            I[i] = up ? mI : sI;
        }
    }
}
__device__ __forceinline__ void xlane_inv_p(ull R[8], ull I[8], int lane, const float2 wcl[5]) {
    #pragma unroll
    for (int st = 0; st < 5; ++st) {
        const int m = 1 << st;
        const float2 w = wcl[4 - st];
        const ull sx  = splat(w.x);
        const ull sy  = splat(w.y);
        const ull syn = splat(-w.y);
        const bool up = (lane & m) != 0;
        #pragma unroll
        for (int i = 0; i < 8; ++i) {
            // conj twiddle on upper lanes before exchange
            const ull mR = pfma(R[i], sx, pmul(I[i], sy));
            const ull mI = pfma(I[i], sx, pmul(R[i], syn));
            const ull vR = up ? mR : R[i];
            const ull vI = up ? mI : I[i];
            const ull oR = pshfl_xor(vR, m);
            const ull oI = pshfl_xor(vI, m);
            const ull aR = padd(vR, oR), aI = padd(vI, oI);
            const ull bR = psub(oR, vR), bI = psub(oI, vI);
            R[i] = up ? bR : aR;
            I[i] = up ? bI : aI;
        }
    }
}
__device__ __forceinline__ void twiddle_fwd_p(ull R[8], ull I[8], const float2 wp[8]) {
    pcmul(R[1], I[1], wp[4].x, wp[4].y); pcmul(R[2], I[2], wp[2].x, wp[2].y);
    pcmul(R[3], I[3], wp[6].x, wp[6].y); pcmul(R[4], I[4], wp[1].x, wp[1].y);
    pcmul(R[5], I[5], wp[5].x, wp[5].y); pcmul(R[6], I[6], wp[3].x, wp[3].y);
    pcmul(R[7], I[7], wp[7].x, wp[7].y);
}
__device__ __forceinline__ void twiddle_inv_p(ull R[8], ull I[8], const float2 wp[8]) {
    pcmulj(R[1], I[1], wp[4].x, wp[4].y); pcmulj(R[2], I[2], wp[2].x, wp[2].y);
    pcmulj(R[3], I[3], wp[6].x, wp[6].y); pcmulj(R[4], I[4], wp[1].x, wp[1].y);
    pcmulj(R[5], I[5], wp[5].x, wp[5].y); pcmulj(R[6], I[6], wp[3].x, wp[3].y);
    pcmulj(R[7], I[7], wp[7].x, wp[7].y);
}
__device__ __forceinline__ void fft256_fwd_p(ull R[8], ull I[8], int lane, const float2 wp[8], const float2 wcl[5]) {
    reg_dif8_p(R, I); twiddle_fwd_p(R, I, wp); xlane_fwd_p(R, I, lane, wcl);
}
__device__ __forceinline__ void fft256_inv_p(ull R[8], ull I[8], int lane, const float2 wp[8], const float2 wcl[5]) {
    xlane_inv_p(R, I, lane, wcl); twiddle_inv_p(R, I, wp); reg_dit8_inv_p(R, I);
}

// ---------------- setup: C~ table via shared root LUT ----------------
__global__ void setup_C_kernel(const float* __restrict__ h_real, const float* __restrict__ h_imag) {
    __shared__ float2 lut[NFFT];
    __shared__ float hr[MTAPS], hi[MTAPS];
    const int n = threadIdx.x;
    float sn, cs;
    __sincosf(-(TWO_PI_F / NFFT) * (float)n, &sn, &cs);
    lut[n] = make_float2(cs, sn);
    if (n < MTAPS) { hr[n] = h_real[n]; hi[n] = h_imag[n]; }
    __syncthreads();
    float sr = 0.0f, si = 0.0f;
    #pragma unroll
    for (int m = 0; m < MTAPS; ++m) {
        const int e = (n * (m - PAD)) & (NFFT - 1);   // exact mod (two's complement)
        const float2 w = lut[e];
        sr = fmaf(hr[m], w.x, fmaf(-hi[m], w.y, sr));
        si = fmaf(hr[m], w.y, fmaf( hi[m], w.x, si));
    }
    g_C[n] = make_float2(sr * (1.0f / NFFT), si * (1.0f / NFFT));
}

// ---------------- kernel 1: warp per (batch, frame), mode-packed ----------------
__global__ __launch_bounds__(128) void eq_frame_kernel(
    const float* __restrict__ x_real,
    const float* __restrict__ x_imag,
    const float* __restrict__ task_info,
    float* __restrict__ out,
    int L, int steps)
{
    const int w = blockIdx.x * 4 + (threadIdx.x >> 5);
    const int lane = threadIdx.x & 31;
    if (w >= BATCH * steps) return;
    const int b = w / steps;
    const int s = w - b * steps;

    // cross-lane stage twiddles
    float2 wcl[5];
    #pragma unroll
    for (int st = 0; st < 5; ++st) {
        const int m = 16 >> st;
        const float ang = -(TWO_PI_F / (2.0f * (float)m)) * (float)(lane & (m - 1));
        __sincosf(ang, &wcl[st].y, &wcl[st].x);
    }
    // per-lane twiddle powers
    float2 wp[8];
    wp[0] = make_float2(1.0f, 0.0f);
    __sincosf(-(TWO_PI_F / 256.0f) * (float)lane, &wp[1].y, &wp[1].x);
    wp[2] = cmulf(wp[1], wp[1]);
    wp[3] = cmulf(wp[2], wp[1]);
    wp[4] = cmulf(wp[2], wp[2]);
    wp[5] = cmulf(wp[4], wp[1]);
    wp[6] = cmulf(wp[3], wp[3]);
    wp[7] = cmulf(wp[4], wp[3]);

    // ---- load frame: packed Re = (re_mode0, re_mode1), Im likewise (direct u64 loads)
    ull R[8], I[8];
    const ull* xr8 = reinterpret_cast<const ull*>(x_real) + (size_t)b * L;
    const ull* xi8 = reinterpret_cast<const ull*>(x_imag) + (size_t)b * L;
    const int base = s * HOP + lane;
    #pragma unroll
    for (int r = 0; r < 8; ++r) {
        R[r] = __ldg(&xr8[base + 32 * r]);
        I[r] = __ldg(&xi8[base + 32 * r]);
    }

    // ---- forward FFT (both modes at once)
    fft256_fwd_p(R, I, lane, wp, wcl);

    // ---- intensity per bin
    float2 Iv[8];
    #pragma unroll
    for (int i = 0; i < 8; ++i) {
        const float2 rr = unpk(R[i]);
        const float2 ii = unpk(I[i]);
        float t = rr.x * rr.x;
        t = fmaf(rr.y, rr.y, t);
        t = fmaf(ii.x, ii.x, t);
        t = fmaf(ii.y, ii.y, t);
        Iv[i] = make_float2(t, 0.0f);
    }

    // ---- phi = FWD( INVraw(I) .* C~ )
    fft256_inv(Iv, lane, wp, wcl);
    #pragma unroll
    for (int r = 0; r < 8; ++r) {
        Iv[r] = cmulf(Iv[r], g_C[lane + 32 * r]);
    }
    fft256_fwd(Iv, lane, wp, wcl);

    // ---- Y = X * (1 + i*P*phi)   (scalar complex factor, applied packed)
    const float P = exp10f(task_info[b * 4] * 0.1f) * 0.5f;
    #pragma unroll
    for (int i = 0; i < 8; ++i) {
        const float fx = fmaf(-P, Iv[i].y, 1.0f);
        const float fy = P * Iv[i].x;
        pcmul(R[i], I[i], fx, fy);
    }

    // ---- inverse FFT (both modes) -> natural time order
    fft256_inv_p(R, I, lane, wp, wcl);

    // ---- write: direct output for singly-covered samples, edges to scratch
    const float sc = 1.0f / (float)NFFT;
    const int Lout = L - OVERLAP;
    float4* out4 = reinterpret_cast<float4*>(out) + (size_t)b * Lout;
    float4* headp = g_head + (size_t)(b * steps + s) * OVERLAP;
    float4* tailp = g_tail + (size_t)(b * steps + s) * OVERLAP;
    #pragma unroll
    for (int r = 0; r < 8; ++r) {
        const int n = lane + 32 * r;
        const float2 rr = unpk(R[r]);
        const float2 ii = unpk(I[r]);
        float4 v;
        v.x = rr.x * sc; v.y = ii.x * sc;   // mode0 (re, im)
        v.z = rr.y * sc; v.w = ii.y * sc;   // mode1 (re, im)
        if (n < OVERLAP && s > 0) {
            headp[n] = v;
        } else if (n >= HOP && s < steps - 1) {
            tailp[n - HOP] = v;
        } else {
            const int lp = s * HOP + n;
            if (lp >= PAD && lp < L - PAD) out4[lp - PAD] = v;
        }
    }
}

// ---------------- kernel 2: combine the 40-sample overlap edges ----------------
__global__ __launch_bounds__(256) void combine_edges_kernel(float* __restrict__ out, int L, int steps) {
    const int idx = blockIdx.x * blockDim.x + threadIdx.x;
    const int per_b = (steps - 1) * OVERLAP;
    if (idx >= BATCH * per_b) return;
    const int b = idx / per_b;
    const int t = idx - b * per_b;
    const int s = t / OVERLAP;
    const int e = t - s * OVERLAP;

    const float4 a = g_tail[(size_t)(b * steps + s) * OVERLAP + e];
    const float4 h = g_head[(size_t)(b * steps + s + 1) * OVERLAP + e];
    float4 v;
    v.x = (a.x + h.x) * 0.5f;
    v.y = (a.y + h.y) * 0.5f;
    v.z = (a.z + h.z) * 0.5f;
    v.w = (a.w + h.w) * 0.5f;

    const int lp = (s + 1) * HOP + e;
    const int Lout = L - OVERLAP;
    reinterpret_cast<float4*>(out)[(size_t)b * Lout + lp - PAD] = v;
}

extern "C" void kernel_launch(void* const* d_in, const int* in_sizes, int n_in,
                              void* d_out, int out_size)
{
    const float* x_real    = (const float*)d_in[0];
    const float* x_imag    = (const float*)d_in[1];
    const float* task_info = (const float*)d_in[2];
    const float* h_real    = (const float*)d_in[3];
    const float* h_imag    = (const float*)d_in[4];

    const int L = in_sizes[0] / (BATCH * 2);
    int steps = (L - NFFT) / HOP + 1;
    if (steps > MAX_STEPS) steps = MAX_STEPS;

    setup_C_kernel<<<1, NFFT>>>(h_real, h_imag);

    const int warps = BATCH * steps;
    eq_frame_kernel<<<(warps + 3) / 4, 128>>>(x_real, x_imag, task_info, (float*)d_out, L, steps);

    const int total2 = BATCH * (steps - 1) * OVERLAP;
    combine_edges_kernel<<<(total2 + 255) / 256, 256>>>((float*)d_out, L, steps);
}